// round 3
// baseline (speedup 1.0000x reference)
#include <cuda_runtime.h>
#include <math.h>

// Problem constants
#define TT   4096           // tokens (2*2048)
#define HH   1024           // hidden
#define DD   2752           // intermediate
#define NE   8              // routed experts
#define KEXP 2              // top-k
#define BM   64
#define BN   64
#define BKK  16
#define ROWCAP (TT*KEXP + NE*BM)   // 8704 padded routed rows

// ---------------- scratch (device globals; allocation-free) ----------------
__device__ int   g_counts[NE];
__device__ int   g_cursor[NE];
__device__ int   g_offsets[NE+1];
__device__ int   g_row_token[ROWCAP];    // padded row -> token (-1 = pad)
__device__ int   g_row_tk[ROWCAP];       // padded row -> t*2+k
__device__ int   g_tok_e[TT*KEXP];       // token,k -> expert
__device__ float g_tok_w[TT*KEXP];       // token,k -> renormalized weight
__device__ float g_hid [(size_t)ROWCAP*DD];   // routed hidden (silu(g)*u)
__device__ float g_shid[(size_t)TT*DD];       // shared-expert hidden
__device__ float g_eo  [(size_t)TT*KEXP*HH];  // routed down outputs per (t,k)

// ---------------- init ----------------
__global__ void init_kernel() {
    int i = blockIdx.x * blockDim.x + threadIdx.x;
    if (i < NE) { g_counts[i] = 0; g_cursor[i] = 0; }
    if (i < ROWCAP) g_row_token[i] = -1;
}

// ---------------- routing: logits -> softmax -> top2 -> counts ----------------
__global__ void route_kernel(const float* __restrict__ x,
                             const float* __restrict__ gw) {
    int t    = blockIdx.x * (blockDim.x >> 5) + (threadIdx.x >> 5);
    int lane = threadIdx.x & 31;
    if (t >= TT) return;
    const float* xr = x + (size_t)t * HH;

    float xs[HH/32];
    #pragma unroll
    for (int i = 0; i < HH/32; i++) xs[i] = xr[lane + 32*i];

    float logit[NE];
    #pragma unroll
    for (int e = 0; e < NE; e++) {
        const float* w = gw + e * HH;
        float s = 0.f;
        #pragma unroll
        for (int i = 0; i < HH/32; i++) s += xs[i] * w[lane + 32*i];
        #pragma unroll
        for (int o = 16; o; o >>= 1) s += __shfl_xor_sync(0xffffffffu, s, o);
        logit[e] = s;
    }

    float m = logit[0];
    #pragma unroll
    for (int e = 1; e < NE; e++) m = fmaxf(m, logit[e]);
    float p[NE], ssum = 0.f;
    #pragma unroll
    for (int e = 0; e < NE; e++) { p[e] = expf(logit[e] - m); ssum += p[e]; }
    float inv = 1.f / ssum;
    #pragma unroll
    for (int e = 0; e < NE; e++) p[e] *= inv;

    int i0 = 0;
    #pragma unroll
    for (int e = 1; e < NE; e++) if (p[e] > p[i0]) i0 = e;
    int i1 = -1;
    #pragma unroll
    for (int e = 0; e < NE; e++)
        if (e != i0 && (i1 < 0 || p[e] > p[i1])) i1 = e;

    float w0 = p[i0], w1 = p[i1];
    float norm = 1.f / (w0 + w1 + 1e-20f);
    w0 *= norm; w1 *= norm;

    if (lane == 0) {
        g_tok_e[t*2]   = i0;  g_tok_e[t*2+1] = i1;
        g_tok_w[t*2]   = w0;  g_tok_w[t*2+1] = w1;
        atomicAdd(&g_counts[i0], 1);
        atomicAdd(&g_counts[i1], 1);
    }
}

// ---------------- scan: BM-padded expert segment offsets ----------------
__global__ void scan_kernel() {
    if (threadIdx.x == 0 && blockIdx.x == 0) {
        int off = 0;
        for (int e = 0; e < NE; e++) {
            g_offsets[e] = off;
            off += ((g_counts[e] + BM - 1) / BM) * BM;
        }
        g_offsets[NE] = off;
    }
}

// ---------------- assign tokens to expert rows ----------------
__global__ void assign_kernel() {
    int idx = blockIdx.x * blockDim.x + threadIdx.x;
    if (idx >= TT*KEXP) return;
    int e   = g_tok_e[idx];
    int pos = atomicAdd(&g_cursor[e], 1);
    int row = g_offsets[e] + pos;
    g_row_token[row] = idx >> 1;
    g_row_tk[row]    = idx;
}

// ---------------- gate+up GEMM, silu epilogue ----------------
// out = silu(X @ Wg) * (X @ Wu), rows grouped by expert (ROUTED) or identity.
template<bool ROUTED>
__global__ void gateup_kernel(const float* __restrict__ X,
                              const float* __restrict__ Wg_base,
                              const float* __restrict__ Wu_base) {
    __shared__ float As[BKK][BM];
    __shared__ float Bg[BKK][BN];
    __shared__ float Bu[BKK][BN];
    __shared__ int   Rtok[BM];

    int row0 = blockIdx.y * BM;
    int n0   = blockIdx.x * BN;

    const float *Wg, *Wu;
    float* outp;
    if (ROUTED) {
        if (row0 >= g_offsets[NE]) return;
        int e = 0;
        #pragma unroll
        for (int i = 1; i < NE; i++) if (row0 >= g_offsets[i]) e = i;
        Wg = Wg_base + (size_t)e * HH * DD;
        Wu = Wu_base + (size_t)e * HH * DD;
        outp = g_hid;
    } else {
        Wg = Wg_base; Wu = Wu_base; outp = g_shid;
    }

    int tid = threadIdx.x;
    if (tid < BM) Rtok[tid] = ROUTED ? g_row_token[row0 + tid] : (row0 + tid);
    __syncthreads();

    int tm = tid >> 4, tn = tid & 15;
    float accg[8][4], accu[8][4];
    #pragma unroll
    for (int i = 0; i < 8; i++)
        #pragma unroll
        for (int j = 0; j < 4; j++) { accg[i][j] = 0.f; accu[i][j] = 0.f; }

    for (int h0 = 0; h0 < HH; h0 += BKK) {
        #pragma unroll
        for (int rep = 0; rep < 2; rep++) {
            int li = tid + rep * 128;            // 0..255
            int r = li >> 2, c4 = li & 3;
            int tok = Rtok[r]; if (tok < 0) tok = 0;
            float4 v = *(const float4*)(X + (size_t)tok * HH + h0 + c4 * 4);
            As[c4*4+0][r] = v.x; As[c4*4+1][r] = v.y;
            As[c4*4+2][r] = v.z; As[c4*4+3][r] = v.w;
        }
        #pragma unroll
        for (int rep = 0; rep < 2; rep++) {
            int li = tid + rep * 128;
            int kr = li >> 4, c = (li & 15) * 4;
            *(float4*)&Bg[kr][c] = *(const float4*)(Wg + (size_t)(h0+kr) * DD + n0 + c);
            *(float4*)&Bu[kr][c] = *(const float4*)(Wu + (size_t)(h0+kr) * DD + n0 + c);
        }
        __syncthreads();
        #pragma unroll
        for (int kk = 0; kk < BKK; kk++) {
            float a[8], bg[4], bu[4];
            *(float4*)(a)     = *(float4*)&As[kk][tm*8];
            *(float4*)(a + 4) = *(float4*)&As[kk][tm*8+4];
            *(float4*)bg = *(float4*)&Bg[kk][tn*4];
            *(float4*)bu = *(float4*)&Bu[kk][tn*4];
            #pragma unroll
            for (int i = 0; i < 8; i++)
                #pragma unroll
                for (int j = 0; j < 4; j++) {
                    accg[i][j] += a[i] * bg[j];
                    accu[i][j] += a[i] * bu[j];
                }
        }
        __syncthreads();
    }

    #pragma unroll
    for (int i = 0; i < 8; i++) {
        int r = tm * 8 + i;
        if (ROUTED && Rtok[r] < 0) continue;
        float4 hv;
        float g, u;
        g = accg[i][0]; u = accu[i][0]; hv.x = g / (1.f + expf(-g)) * u;
        g = accg[i][1]; u = accu[i][1]; hv.y = g / (1.f + expf(-g)) * u;
        g = accg[i][2]; u = accu[i][2]; hv.z = g / (1.f + expf(-g)) * u;
        g = accg[i][3]; u = accu[i][3]; hv.w = g / (1.f + expf(-g)) * u;
        *(float4*)(outp + (size_t)(row0 + r) * DD + n0 + tn * 4) = hv;
    }
}

// ---------------- down GEMM ----------------
// ROUTED: g_eo[tk] = hid_row @ we_down[e]
// !ROUTED: out[t]  = shid[t] @ sw_down + w0*eo[t,0] + w1*eo[t,1]
template<bool ROUTED>
__global__ void down_kernel(const float* __restrict__ Wd_base,
                            float* __restrict__ d_out) {
    __shared__ float As[BKK][BM];
    __shared__ float Bs[BKK][BN];
    __shared__ int   Rinfo[BM];

    int row0 = blockIdx.y * BM;
    int n0   = blockIdx.x * BN;

    const float *A, *Wd;
    if (ROUTED) {
        if (row0 >= g_offsets[NE]) return;
        int e = 0;
        #pragma unroll
        for (int i = 1; i < NE; i++) if (row0 >= g_offsets[i]) e = i;
        Wd = Wd_base + (size_t)e * DD * HH;
        A  = g_hid;
    } else {
        Wd = Wd_base;
        A  = g_shid;
    }

    int tid = threadIdx.x;
    if (tid < BM) {
        if (ROUTED) {
            int tok = g_row_token[row0 + tid];
            Rinfo[tid] = (tok < 0) ? -1 : g_row_tk[row0 + tid];
        } else {
            Rinfo[tid] = row0 + tid;
        }
    }
    __syncthreads();

    int tm = tid >> 4, tn = tid & 15;
    float acc[8][4];
    #pragma unroll
    for (int i = 0; i < 8; i++)
        #pragma unroll
        for (int j = 0; j < 4; j++) acc[i][j] = 0.f;

    for (int h0 = 0; h0 < DD; h0 += BKK) {
        #pragma unroll
        for (int rep = 0; rep < 2; rep++) {
            int li = tid + rep * 128;
            int r = li >> 2, c4 = li & 3;
            float4 v = *(const float4*)(A + (size_t)(row0 + r) * DD + h0 + c4 * 4);
            As[c4*4+0][r] = v.x; As[c4*4+1][r] = v.y;
            As[c4*4+2][r] = v.z; As[c4*4+3][r] = v.w;
        }
        #pragma unroll
        for (int rep = 0; rep < 2; rep++) {
            int li = tid + rep * 128;
            int kr = li >> 4, c = (li & 15) * 4;
            *(float4*)&Bs[kr][c] = *(const float4*)(Wd + (size_t)(h0+kr) * HH + n0 + c);
        }
        __syncthreads();
        #pragma unroll
        for (int kk = 0; kk < BKK; kk++) {
            float a[8], b[4];
            *(float4*)(a)     = *(float4*)&As[kk][tm*8];
            *(float4*)(a + 4) = *(float4*)&As[kk][tm*8+4];
            *(float4*)b = *(float4*)&Bs[kk][tn*4];
            #pragma unroll
            for (int i = 0; i < 8; i++)
                #pragma unroll
                for (int j = 0; j < 4; j++)
                    acc[i][j] += a[i] * b[j];
        }
        __syncthreads();
    }

    #pragma unroll
    for (int i = 0; i < 8; i++) {
        int r = tm * 8 + i;
        int info = Rinfo[r];
        if (ROUTED) {
            if (info < 0) continue;
            float4 v; v.x = acc[i][0]; v.y = acc[i][1]; v.z = acc[i][2]; v.w = acc[i][3];
            *(float4*)(g_eo + (size_t)info * HH + n0 + tn * 4) = v;
        } else {
            int t = info;
            float w0 = g_tok_w[t*2], w1 = g_tok_w[t*2+1];
            const float* e0 = g_eo + (size_t)(t*2)   * HH + n0 + tn * 4;
            const float* e1 = g_eo + (size_t)(t*2+1) * HH + n0 + tn * 4;
            float4 v0 = *(const float4*)e0;
            float4 v1 = *(const float4*)e1;
            float4 o;
            o.x = acc[i][0] + w0 * v0.x + w1 * v1.x;
            o.y = acc[i][1] + w0 * v0.y + w1 * v1.y;
            o.z = acc[i][2] + w0 * v0.z + w1 * v1.z;
            o.w = acc[i][3] + w0 * v0.w + w1 * v1.w;
            *(float4*)(d_out + (size_t)t * HH + n0 + tn * 4) = o;
        }
    }
}

// ---------------- launch ----------------
extern "C" void kernel_launch(void* const* d_in, const int* in_sizes, int n_in,
                              void* d_out, int out_size) {
    const float* x       = (const float*)d_in[0];
    const float* gate_w  = (const float*)d_in[1];
    const float* we_gate = (const float*)d_in[2];
    const float* we_up   = (const float*)d_in[3];
    const float* we_down = (const float*)d_in[4];
    const float* sw_gate = (const float*)d_in[5];
    const float* sw_up   = (const float*)d_in[6];
    const float* sw_down = (const float*)d_in[7];
    float* out = (float*)d_out;

    init_kernel<<<(ROWCAP + 255) / 256, 256>>>();
    route_kernel<<<TT / 8, 256>>>(x, gate_w);
    scan_kernel<<<1, 32>>>();
    assign_kernel<<<(TT * KEXP + 255) / 256, 256>>>();

    dim3 blk(128);
    gateup_kernel<true ><<<dim3(DD / BN, ROWCAP / BM), blk>>>(x, we_gate, we_up);
    gateup_kernel<false><<<dim3(DD / BN, TT / BM),     blk>>>(x, sw_gate, sw_up);
    down_kernel<true ><<<dim3(HH / BN, ROWCAP / BM), blk>>>(we_down, out);
    down_kernel<false><<<dim3(HH / BN, TT / BM),     blk>>>(sw_down, out);
}

// round 7
// speedup vs baseline: 2.7558x; 2.7558x over previous
#include <cuda_runtime.h>
#include <cstdint>
#include <math.h>

#define TT 4096
#define HH 1024
#define DD 2752
#define NE 8
#define BM 128
#define ROWCAP (TT*2 + NE*BM)   // 9216

#define GU_S 2
#define DN_S 2
#define AS_F (128*36)            // 4608 floats
#define BS_F (64*36)             // 2304 floats
#define GU_STAGEF (AS_F + 2*BS_F)  // 9216 floats / 36864 B
#define DN_STAGEF (AS_F + AS_F)    // A(128x32) + B(128x32), 9216 floats
#define GU_SMEMB (GU_S*GU_STAGEF*4)
#define DN_SMEMB (DN_S*DN_STAGEF*4)

// ---------------- scratch ----------------
__device__ int   g_counts[NE];
__device__ int   g_cursor[NE];
__device__ int   g_offsets[NE+1];
__device__ int   g_row_token[ROWCAP];
__device__ int   g_row_tk[ROWCAP];
__device__ int   g_tok_e[TT*2];
__device__ float g_tok_w[TT*2];
__device__ float g_xc [(size_t)TT*HH];      // tf32-rounded x
__device__ float g_wgT[(size_t)NE*DD*HH];
__device__ float g_wuT[(size_t)NE*DD*HH];
__device__ float g_wdT[(size_t)NE*HH*DD];
__device__ float g_sgT[(size_t)DD*HH];
__device__ float g_suT[(size_t)DD*HH];
__device__ float g_sdT[(size_t)HH*DD];
__device__ float g_hid [(size_t)ROWCAP*DD];
__device__ float g_shid[(size_t)TT*DD];
__device__ float g_eo  [(size_t)TT*2*HH];

// ---------------- helpers ----------------
__device__ __forceinline__ uint32_t s2u(const void* p){
  uint32_t a; asm("{ .reg .u64 t; cvta.to.shared.u64 t, %1; cvt.u32.u64 %0, t; }":"=r"(a):"l"(p)); return a;
}
__device__ __forceinline__ float totf(float x){
  uint32_t u; asm("cvt.rna.tf32.f32 %0, %1;" : "=r"(u) : "f"(x));
  return __uint_as_float(u);
}
__device__ __forceinline__ void cpa16(uint32_t d, const void* s){
  asm volatile("cp.async.cg.shared.global [%0], [%1], 16;"::"r"(d),"l"(s));
}
__device__ __forceinline__ void cpcommit(){ asm volatile("cp.async.commit_group;"); }
__device__ __forceinline__ void cpwait(int allow){
  if (allow <= 0)      asm volatile("cp.async.wait_group 0;");
  else                 asm volatile("cp.async.wait_group 1;");
}
__device__ __forceinline__ void mma8(float* c, const uint32_t* a, const uint32_t* b){
  asm volatile("mma.sync.aligned.m16n8k8.row.col.f32.tf32.tf32.f32 "
    "{%0,%1,%2,%3},{%4,%5,%6,%7},{%8,%9},{%0,%1,%2,%3};"
    : "+f"(c[0]),"+f"(c[1]),"+f"(c[2]),"+f"(c[3])
    : "r"(a[0]),"r"(a[1]),"r"(a[2]),"r"(a[3]),"r"(b[0]),"r"(b[1]));
}

// ---------------- routing ----------------
__global__ void init_kernel(){
  int i = blockIdx.x*blockDim.x + threadIdx.x;
  if (i < NE){ g_counts[i]=0; g_cursor[i]=0; }
  if (i < ROWCAP) g_row_token[i] = -1;
}

__global__ void route_kernel(const float* __restrict__ x, const float* __restrict__ gw){
  int t = blockIdx.x*(blockDim.x>>5) + (threadIdx.x>>5);
  int lane = threadIdx.x & 31;
  if (t >= TT) return;
  const float* xr = x + (size_t)t*HH;
  float xs[HH/32];
  #pragma unroll
  for (int i=0;i<HH/32;i++) xs[i] = xr[lane+32*i];
  float logit[NE];
  #pragma unroll
  for (int e=0;e<NE;e++){
    const float* w = gw + e*HH;
    float s = 0.f;
    #pragma unroll
    for (int i=0;i<HH/32;i++) s += xs[i]*w[lane+32*i];
    #pragma unroll
    for (int o=16;o;o>>=1) s += __shfl_xor_sync(0xffffffffu, s, o);
    logit[e] = s;
  }
  float m = logit[0];
  #pragma unroll
  for (int e=1;e<NE;e++) m = fmaxf(m, logit[e]);
  float p[NE], ssum = 0.f;
  #pragma unroll
  for (int e=0;e<NE;e++){ p[e] = expf(logit[e]-m); ssum += p[e]; }
  float inv = 1.f/ssum;
  #pragma unroll
  for (int e=0;e<NE;e++) p[e] *= inv;
  int i0 = 0;
  #pragma unroll
  for (int e=1;e<NE;e++) if (p[e] > p[i0]) i0 = e;
  int i1 = -1;
  #pragma unroll
  for (int e=0;e<NE;e++) if (e != i0 && (i1 < 0 || p[e] > p[i1])) i1 = e;
  float w0 = p[i0], w1 = p[i1];
  float nrm = 1.f/(w0+w1+1e-20f);
  w0 *= nrm; w1 *= nrm;
  if (lane == 0){
    g_tok_e[t*2] = i0; g_tok_e[t*2+1] = i1;
    g_tok_w[t*2] = w0; g_tok_w[t*2+1] = w1;
    atomicAdd(&g_counts[i0],1);
    atomicAdd(&g_counts[i1],1);
  }
}

__global__ void scan_kernel(){
  if (threadIdx.x==0 && blockIdx.x==0){
    int off = 0;
    for (int e=0;e<NE;e++){
      g_offsets[e] = off;
      off += ((g_counts[e]+BM-1)/BM)*BM;
    }
    g_offsets[NE] = off;
  }
}

__global__ void assign_kernel(){
  int idx = blockIdx.x*blockDim.x + threadIdx.x;
  if (idx >= TT*2) return;
  int e = g_tok_e[idx];
  int pos = atomicAdd(&g_cursor[e],1);
  int row = g_offsets[e] + pos;
  g_row_token[row] = idx>>1;
  g_row_tk[row] = idx;
}

// ---------------- x -> tf32-rounded copy ----------------
__global__ void convx_k(const float* __restrict__ x){
  size_t i = ((size_t)blockIdx.x*blockDim.x + threadIdx.x)*4;
  if (i >= (size_t)TT*HH) return;
  float4 v = *(const float4*)(x+i);
  v.x = totf(v.x); v.y = totf(v.y); v.z = totf(v.z); v.w = totf(v.w);
  *(float4*)(g_xc+i) = v;
}

// ---------------- weight transpose + tf32 round ----------------
__global__ void transpose_k(const float* __restrict__ src, int which, int R, int C){
  float* dst = which==0 ? g_wgT : which==1 ? g_wuT : which==2 ? g_wdT :
               which==3 ? g_sgT : which==4 ? g_suT : g_sdT;
  __shared__ float t[32][33];
  size_t boff = (size_t)blockIdx.z * R * C;
  src += boff; dst += boff;
  int x = blockIdx.x*32 + threadIdx.x;
  int y0 = blockIdx.y*32;
  #pragma unroll
  for (int j=0;j<32;j+=8)
    t[threadIdx.y+j][threadIdx.x] = src[(size_t)(y0+threadIdx.y+j)*C + x];
  __syncthreads();
  int xx = blockIdx.y*32 + threadIdx.x;
  int yy0 = blockIdx.x*32;
  #pragma unroll
  for (int j=0;j<32;j+=8)
    dst[(size_t)(yy0+threadIdx.y+j)*R + xx] = totf(t[threadIdx.x][threadIdx.y+j]);
}

// ---------------- gate+up GEMM: 128x64 tile, dual-B, fused silu ----------------
template<bool ROUTED>
__global__ void __launch_bounds__(256,2) gu_mma(){
  extern __shared__ float sm[];
  __shared__ int rtok[BM];
  const int tid = threadIdx.x, lane = tid&31, wid = tid>>5;
  const int wr = wid>>1, wc = wid&1;
  const int gr = lane>>2, gc = lane&3;
  const int row0 = blockIdx.y*BM, n0 = blockIdx.x*64;
  if (ROUTED && row0 >= g_offsets[NE]) return;

  const float *Wg, *Wu; float* Out;
  if (ROUTED){
    int e = 0;
    #pragma unroll
    for (int i=1;i<NE;i++) if (row0 >= g_offsets[i]) e = i;
    Wg = g_wgT + (size_t)e*DD*HH;
    Wu = g_wuT + (size_t)e*DD*HH;
    Out = g_hid;
  } else { Wg = g_sgT; Wu = g_suT; Out = g_shid; }

  if (tid < BM){
    int t = ROUTED ? g_row_token[row0+tid] : (row0+tid);
    rtok[tid] = t < 0 ? 0 : t;
  }
  __syncthreads();

  const int NCH = HH/32;   // 32
  auto ld = [&](int c, int s){
    float* S = sm + s*GU_STAGEF;
    uint32_t sA = s2u(S);
    uint32_t sG = s2u(S + AS_F);
    uint32_t sU = s2u(S + AS_F + BS_F);
    int k0 = c*32;
    #pragma unroll
    for (int j=0;j<4;j++){
      int q = tid + 256*j, r = q>>3, sg = q&7;
      cpa16(sA + r*144 + sg*16, g_xc + (size_t)rtok[r]*HH + k0 + sg*4);
    }
    #pragma unroll
    for (int j=0;j<2;j++){
      int q = tid + 256*j, r = q>>3, sg = q&7;
      cpa16(sG + r*144 + sg*16, Wg + (size_t)(n0+r)*HH + k0 + sg*4);
      cpa16(sU + r*144 + sg*16, Wu + (size_t)(n0+r)*HH + k0 + sg*4);
    }
    cpcommit();
  };
  #pragma unroll
  for (int s=0;s<GU_S;s++) ld(s, s);

  float accg[2][4][4], accu[2][4][4];
  #pragma unroll
  for (int a=0;a<2;a++)
    #pragma unroll
    for (int b=0;b<4;b++)
      #pragma unroll
      for (int d=0;d<4;d++){ accg[a][b][d]=0.f; accu[a][b][d]=0.f; }

  for (int c=0;c<NCH;c++){
    cpwait((NCH-1-c) < (GU_S-1) ? (NCH-1-c) : (GU_S-1));
    __syncthreads();
    const float* S  = sm + (c%GU_S)*GU_STAGEF;
    const float* As = S;
    const float* Bg = S + AS_F;
    const float* Bu = S + AS_F + BS_F;
    #pragma unroll
    for (int ks=0;ks<4;ks++){
      int k = ks*8;
      uint32_t a[2][4];
      #pragma unroll
      for (int mt=0;mt<2;mt++){
        int r0 = wr*32 + mt*16;
        a[mt][0] = __float_as_uint(As[(r0+gr  )*36 + k+gc  ]);
        a[mt][1] = __float_as_uint(As[(r0+gr+8)*36 + k+gc  ]);
        a[mt][2] = __float_as_uint(As[(r0+gr  )*36 + k+gc+4]);
        a[mt][3] = __float_as_uint(As[(r0+gr+8)*36 + k+gc+4]);
      }
      #pragma unroll
      for (int nt=0;nt<4;nt++){
        int n = wc*32 + nt*8 + gr;
        uint32_t bg[2] = { __float_as_uint(Bg[n*36 + k+gc]), __float_as_uint(Bg[n*36 + k+gc+4]) };
        uint32_t bu[2] = { __float_as_uint(Bu[n*36 + k+gc]), __float_as_uint(Bu[n*36 + k+gc+4]) };
        mma8(accg[0][nt], a[0], bg);
        mma8(accg[1][nt], a[1], bg);
        mma8(accu[0][nt], a[0], bu);
        mma8(accu[1][nt], a[1], bu);
      }
    }
    __syncthreads();
    if (c+GU_S < NCH) ld(c+GU_S, c%GU_S);
  }

  // epilogue: silu(g)*u in registers, tf32-round (feeds next GEMM), float2 stores
  #pragma unroll
  for (int mt=0;mt<2;mt++)
    #pragma unroll
    for (int nt=0;nt<4;nt++){
      int r   = row0 + wr*32 + mt*16 + gr;
      int col = n0 + wc*32 + nt*8 + 2*gc;
      float g0 = accg[mt][nt][0], u0 = accu[mt][nt][0];
      float g1 = accg[mt][nt][1], u1 = accu[mt][nt][1];
      float2 v0 = make_float2(totf(g0/(1.f+expf(-g0))*u0), totf(g1/(1.f+expf(-g1))*u1));
      *(float2*)(Out + (size_t)r*DD + col) = v0;
      float g2 = accg[mt][nt][2], u2 = accu[mt][nt][2];
      float g3 = accg[mt][nt][3], u3 = accu[mt][nt][3];
      float2 v1 = make_float2(totf(g2/(1.f+expf(-g2))*u2), totf(g3/(1.f+expf(-g3))*u3));
      *(float2*)(Out + (size_t)(r+8)*DD + col) = v1;
    }
}

// ---------------- down GEMM: 128x128 tile ----------------
// MODE 0: g_eo[tk] = hid row @ we_downT[e];  MODE 1: out = shid@sw_downT + w0*eo0 + w1*eo1
template<int MODE>
__global__ void __launch_bounds__(256,2) dn_mma(float* __restrict__ OutTok){
  extern __shared__ float sm[];
  __shared__ int s_tk[BM];
  const int tid = threadIdx.x, lane = tid&31, wid = tid>>5;
  const int wr = wid>>1, wc = wid&1;
  const int gr = lane>>2, gc = lane&3;
  const int row0 = blockIdx.y*BM, n0 = blockIdx.x*128;
  if (MODE==0 && row0 >= g_offsets[NE]) return;

  const float *A, *Wd;
  if (MODE == 0){
    int e = 0;
    #pragma unroll
    for (int i=1;i<NE;i++) if (row0 >= g_offsets[i]) e = i;
    Wd = g_wdT + (size_t)e*HH*DD;
    A = g_hid;
  } else { Wd = g_sdT; A = g_shid; }

  if (tid < BM)
    s_tk[tid] = (MODE==0) ? ((g_row_token[row0+tid] < 0) ? -1 : g_row_tk[row0+tid]) : 0;
  __syncthreads();

  const int NCH = DD/32;   // 86
  auto ld = [&](int c, int s){
    float* S = sm + s*DN_STAGEF;
    uint32_t sA = s2u(S);
    uint32_t sB = s2u(S + AS_F);
    int k0 = c*32;
    #pragma unroll
    for (int j=0;j<4;j++){
      int q = tid + 256*j, r = q>>3, sg = q&7;
      cpa16(sA + r*144 + sg*16, A  + (size_t)(row0+r)*DD + k0 + sg*4);
      cpa16(sB + r*144 + sg*16, Wd + (size_t)(n0 +r)*DD + k0 + sg*4);
    }
    cpcommit();
  };
  #pragma unroll
  for (int s=0;s<DN_S;s++) ld(s, s);

  float acc[2][8][4];
  #pragma unroll
  for (int a=0;a<2;a++)
    #pragma unroll
    for (int b=0;b<8;b++)
      #pragma unroll
      for (int d=0;d<4;d++) acc[a][b][d]=0.f;

  for (int c=0;c<NCH;c++){
    cpwait((NCH-1-c) < (DN_S-1) ? (NCH-1-c) : (DN_S-1));
    __syncthreads();
    const float* S  = sm + (c%DN_S)*DN_STAGEF;
    const float* As = S;
    const float* Bs = S + AS_F;
    #pragma unroll
    for (int ks=0;ks<4;ks++){
      int k = ks*8;
      uint32_t a[2][4];
      #pragma unroll
      for (int mt=0;mt<2;mt++){
        int r0 = wr*32 + mt*16;
        a[mt][0] = __float_as_uint(As[(r0+gr  )*36 + k+gc  ]);
        a[mt][1] = __float_as_uint(As[(r0+gr+8)*36 + k+gc  ]);
        a[mt][2] = __float_as_uint(As[(r0+gr  )*36 + k+gc+4]);
        a[mt][3] = __float_as_uint(As[(r0+gr+8)*36 + k+gc+4]);
      }
      #pragma unroll
      for (int nt=0;nt<8;nt++){
        int n = wc*64 + nt*8 + gr;
        uint32_t b[2] = { __float_as_uint(Bs[n*36 + k+gc]), __float_as_uint(Bs[n*36 + k+gc+4]) };
        mma8(acc[0][nt], a[0], b);
        mma8(acc[1][nt], a[1], b);
      }
    }
    __syncthreads();
    if (c+DN_S < NCH) ld(c+DN_S, c%DN_S);
  }

  #pragma unroll
  for (int mt=0;mt<2;mt++)
    #pragma unroll
    for (int nt=0;nt<8;nt++){
      int rl  = wr*32 + mt*16 + gr;
      int col = n0 + wc*64 + nt*8 + 2*gc;
      if (MODE == 0){
        int tk0 = s_tk[rl], tk1 = s_tk[rl+8];
        if (tk0 >= 0)
          *(float2*)(g_eo + (size_t)tk0*HH + col) = make_float2(acc[mt][nt][0], acc[mt][nt][1]);
        if (tk1 >= 0)
          *(float2*)(g_eo + (size_t)tk1*HH + col) = make_float2(acc[mt][nt][2], acc[mt][nt][3]);
      } else {
        int t0 = row0 + rl, t1 = t0 + 8;
        float w00 = g_tok_w[t0*2], w01 = g_tok_w[t0*2+1];
        float w10 = g_tok_w[t1*2], w11 = g_tok_w[t1*2+1];
        float2 a0 = *(const float2*)(g_eo + (size_t)(t0*2  )*HH + col);
        float2 b0 = *(const float2*)(g_eo + (size_t)(t0*2+1)*HH + col);
        float2 a1 = *(const float2*)(g_eo + (size_t)(t1*2  )*HH + col);
        float2 b1 = *(const float2*)(g_eo + (size_t)(t1*2+1)*HH + col);
        float2 o0 = make_float2(acc[mt][nt][0] + w00*a0.x + w01*b0.x,
                                acc[mt][nt][1] + w00*a0.y + w01*b0.y);
        float2 o1 = make_float2(acc[mt][nt][2] + w10*a1.x + w11*b1.x,
                                acc[mt][nt][3] + w10*a1.y + w11*b1.y);
        *(float2*)(OutTok + (size_t)t0*HH + col) = o0;
        *(float2*)(OutTok + (size_t)t1*HH + col) = o1;
      }
    }
}

// ---------------- launch ----------------
extern "C" void kernel_launch(void* const* d_in, const int* in_sizes, int n_in,
                              void* d_out, int out_size) {
  const float* x       = (const float*)d_in[0];
  const float* gate_w  = (const float*)d_in[1];
  const float* we_gate = (const float*)d_in[2];
  const float* we_up   = (const float*)d_in[3];
  const float* we_down = (const float*)d_in[4];
  const float* sw_gate = (const float*)d_in[5];
  const float* sw_up   = (const float*)d_in[6];
  const float* sw_down = (const float*)d_in[7];
  float* out = (float*)d_out;

  cudaFuncSetAttribute(gu_mma<true >, cudaFuncAttributeMaxDynamicSharedMemorySize, GU_SMEMB);
  cudaFuncSetAttribute(gu_mma<false>, cudaFuncAttributeMaxDynamicSharedMemorySize, GU_SMEMB);
  cudaFuncSetAttribute(dn_mma<0>,     cudaFuncAttributeMaxDynamicSharedMemorySize, DN_SMEMB);
  cudaFuncSetAttribute(dn_mma<1>,     cudaFuncAttributeMaxDynamicSharedMemorySize, DN_SMEMB);

  init_kernel<<<(ROWCAP+255)/256, 256>>>();
  route_kernel<<<TT/8, 256>>>(x, gate_w);
  scan_kernel<<<1, 32>>>();
  assign_kernel<<<(TT*2+255)/256, 256>>>();
  convx_k<<<(TT*HH/4+255)/256, 256>>>(x);

  dim3 tb(32, 8);
  transpose_k<<<dim3(DD/32, HH/32, NE), tb>>>(we_gate, 0, HH, DD);
  transpose_k<<<dim3(DD/32, HH/32, NE), tb>>>(we_up,   1, HH, DD);
  transpose_k<<<dim3(HH/32, DD/32, NE), tb>>>(we_down, 2, DD, HH);
  transpose_k<<<dim3(DD/32, HH/32, 1),  tb>>>(sw_gate, 3, HH, DD);
  transpose_k<<<dim3(DD/32, HH/32, 1),  tb>>>(sw_up,   4, HH, DD);
  transpose_k<<<dim3(HH/32, DD/32, 1),  tb>>>(sw_down, 5, DD, HH);

  gu_mma<true ><<<dim3(DD/64, ROWCAP/BM), 256, GU_SMEMB>>>();
  gu_mma<false><<<dim3(DD/64, TT/BM),     256, GU_SMEMB>>>();
  dn_mma<0><<<dim3(HH/128, ROWCAP/BM), 256, DN_SMEMB>>>(nullptr);
  dn_mma<1><<<dim3(HH/128, TT/BM),     256, DN_SMEMB>>>(out);
}

// round 8
// speedup vs baseline: 2.9007x; 1.0526x over previous
#include <cuda_runtime.h>
#include <cstdint>
#include <math.h>

#define TT 4096
#define HH 1024
#define DD 2752
#define NE 8
#define BM 128
#define ROWCAP (TT*2 + NE*BM)   // 9216

#define GU_S 2
#define DN_S 2
#define RSTR 40                    // smem row stride in floats (mod-32 banks = 8)
#define AS_F (128*RSTR)            // 5120 floats
#define BS_F (64*RSTR)             // 2560 floats
#define GU_STAGEF (AS_F + 2*BS_F)  // 10240 floats / 40960 B
#define DN_STAGEF (2*AS_F)         // 10240 floats
#define GU_SMEMB (GU_S*GU_STAGEF*4)   // 81920
#define DN_SMEMB (DN_S*DN_STAGEF*4)   // 81920

// ---------------- scratch ----------------
__device__ int   g_counts[NE];
__device__ int   g_cursor[NE];
__device__ int   g_offsets[NE+1];
__device__ int   g_row_token[ROWCAP];
__device__ int   g_row_tk[ROWCAP];
__device__ int   g_tok_e[TT*2];
__device__ float g_tok_w[TT*2];
__device__ float g_xc [(size_t)TT*HH];      // tf32-rounded, k-permuted x
__device__ float g_wgT[(size_t)NE*DD*HH];   // [D][H] k-permuted on H
__device__ float g_wuT[(size_t)NE*DD*HH];
__device__ float g_wdT[(size_t)NE*HH*DD];   // [H][D] k-permuted on D
__device__ float g_sgT[(size_t)DD*HH];
__device__ float g_suT[(size_t)DD*HH];
__device__ float g_sdT[(size_t)HH*DD];
__device__ float g_hid [(size_t)ROWCAP*DD]; // k-permuted on D
__device__ float g_shid[(size_t)TT*DD];     // k-permuted on D
__device__ float g_eo  [(size_t)TT*2*HH];   // plain layout

// ---------------- helpers ----------------
__device__ __forceinline__ uint32_t s2u(const void* p){
  uint32_t a; asm("{ .reg .u64 t; cvta.to.shared.u64 t, %1; cvt.u32.u64 %0, t; }":"=r"(a):"l"(p)); return a;
}
__device__ __forceinline__ float totf(float x){
  uint32_t u; asm("cvt.rna.tf32.f32 %0, %1;" : "=r"(u) : "f"(x));
  return __uint_as_float(u);
}
__device__ __forceinline__ int kperm(int c){ return ((c&3)<<1) | ((c>>2)&1); }  // within 8-group
__device__ __forceinline__ void cpa16(uint32_t d, const void* s){
  asm volatile("cp.async.cg.shared.global [%0], [%1], 16;"::"r"(d),"l"(s));
}
__device__ __forceinline__ void cpcommit(){ asm volatile("cp.async.commit_group;"); }
__device__ __forceinline__ void cpwait(int allow){
  if (allow <= 0)      asm volatile("cp.async.wait_group 0;");
  else                 asm volatile("cp.async.wait_group 1;");
}
__device__ __forceinline__ void mma8(float* c, const uint32_t* a, const uint32_t* b){
  asm volatile("mma.sync.aligned.m16n8k8.row.col.f32.tf32.tf32.f32 "
    "{%0,%1,%2,%3},{%4,%5,%6,%7},{%8,%9},{%0,%1,%2,%3};"
    : "+f"(c[0]),"+f"(c[1]),"+f"(c[2]),"+f"(c[3])
    : "r"(a[0]),"r"(a[1]),"r"(a[2]),"r"(a[3]),"r"(b[0]),"r"(b[1]));
}

// ---------------- routing ----------------
__global__ void init_kernel(){
  int i = blockIdx.x*blockDim.x + threadIdx.x;
  if (i < NE){ g_counts[i]=0; g_cursor[i]=0; }
  if (i < ROWCAP) g_row_token[i] = -1;
}

__global__ void route_kernel(const float* __restrict__ x, const float* __restrict__ gw){
  int t = blockIdx.x*(blockDim.x>>5) + (threadIdx.x>>5);
  int lane = threadIdx.x & 31;
  if (t >= TT) return;
  const float* xr = x + (size_t)t*HH;
  float xs[HH/32];
  #pragma unroll
  for (int i=0;i<HH/32;i++) xs[i] = xr[lane+32*i];
  float logit[NE];
  #pragma unroll
  for (int e=0;e<NE;e++){
    const float* w = gw + e*HH;
    float s = 0.f;
    #pragma unroll
    for (int i=0;i<HH/32;i++) s += xs[i]*w[lane+32*i];
    #pragma unroll
    for (int o=16;o;o>>=1) s += __shfl_xor_sync(0xffffffffu, s, o);
    logit[e] = s;
  }
  float m = logit[0];
  #pragma unroll
  for (int e=1;e<NE;e++) m = fmaxf(m, logit[e]);
  float p[NE], ssum = 0.f;
  #pragma unroll
  for (int e=0;e<NE;e++){ p[e] = expf(logit[e]-m); ssum += p[e]; }
  float inv = 1.f/ssum;
  #pragma unroll
  for (int e=0;e<NE;e++) p[e] *= inv;
  int i0 = 0;
  #pragma unroll
  for (int e=1;e<NE;e++) if (p[e] > p[i0]) i0 = e;
  int i1 = -1;
  #pragma unroll
  for (int e=0;e<NE;e++) if (e != i0 && (i1 < 0 || p[e] > p[i1])) i1 = e;
  float w0 = p[i0], w1 = p[i1];
  float nrm = 1.f/(w0+w1+1e-20f);
  w0 *= nrm; w1 *= nrm;
  if (lane == 0){
    g_tok_e[t*2] = i0; g_tok_e[t*2+1] = i1;
    g_tok_w[t*2] = w0; g_tok_w[t*2+1] = w1;
    atomicAdd(&g_counts[i0],1);
    atomicAdd(&g_counts[i1],1);
  }
}

__global__ void scan_kernel(){
  if (threadIdx.x==0 && blockIdx.x==0){
    int off = 0;
    for (int e=0;e<NE;e++){
      g_offsets[e] = off;
      off += ((g_counts[e]+BM-1)/BM)*BM;
    }
    g_offsets[NE] = off;
  }
}

__global__ void assign_kernel(){
  int idx = blockIdx.x*blockDim.x + threadIdx.x;
  if (idx >= TT*2) return;
  int e = g_tok_e[idx];
  int pos = atomicAdd(&g_cursor[e],1);
  int row = g_offsets[e] + pos;
  g_row_token[row] = idx>>1;
  g_row_tk[row] = idx;
}

// ---------------- x -> tf32-rounded, k-permuted copy ----------------
// out group [i0..i7] = [v0, v4, v1, v5, v2, v6, v3, v7]
__global__ void convx_k(const float* __restrict__ x){
  size_t i = ((size_t)blockIdx.x*blockDim.x + threadIdx.x)*8;
  if (i >= (size_t)TT*HH) return;
  float4 v0 = *(const float4*)(x+i);
  float4 v1 = *(const float4*)(x+i+4);
  float4 o0 = make_float4(totf(v0.x), totf(v1.x), totf(v0.y), totf(v1.y));
  float4 o1 = make_float4(totf(v0.z), totf(v1.z), totf(v0.w), totf(v1.w));
  *(float4*)(g_xc+i)   = o0;
  *(float4*)(g_xc+i+4) = o1;
}

// ---------------- weight transpose + tf32 round + k-permute ----------------
__global__ void transpose_k(const float* __restrict__ src, int which, int R, int C){
  float* dst = which==0 ? g_wgT : which==1 ? g_wuT : which==2 ? g_wdT :
               which==3 ? g_sgT : which==4 ? g_suT : g_sdT;
  __shared__ float t[32][33];
  size_t boff = (size_t)blockIdx.z * R * C;
  src += boff; dst += boff;
  int x = blockIdx.x*32 + threadIdx.x;
  int y0 = blockIdx.y*32;
  #pragma unroll
  for (int j=0;j<32;j+=8)
    t[threadIdx.y+j][threadIdx.x] = src[(size_t)(y0+threadIdx.y+j)*C + x];
  __syncthreads();
  int xxl = blockIdx.y*32 + threadIdx.x;            // logical k index
  int xx  = (xxl & ~7) | kperm(xxl & 7);            // physical (permuted)
  int yy0 = blockIdx.x*32;
  #pragma unroll
  for (int j=0;j<32;j+=8)
    dst[(size_t)(yy0+threadIdx.y+j)*R + xx] = totf(t[threadIdx.x][threadIdx.y+j]);
}

// ---------------- gate+up GEMM: 128x64 tile, dual-B, fused silu ----------------
template<bool ROUTED>
__global__ void __launch_bounds__(256,2) gu_mma(){
  extern __shared__ float sm[];
  __shared__ int rtok[BM];
  const int tid = threadIdx.x, lane = tid&31, wid = tid>>5;
  const int wr = wid>>1, wc = wid&1;
  const int gr = lane>>2, gc = lane&3;
  const int row0 = blockIdx.y*BM, n0 = blockIdx.x*64;
  if (ROUTED && row0 >= g_offsets[NE]) return;

  const float *Wg, *Wu; float* Out;
  if (ROUTED){
    int e = 0;
    #pragma unroll
    for (int i=1;i<NE;i++) if (row0 >= g_offsets[i]) e = i;
    Wg = g_wgT + (size_t)e*DD*HH;
    Wu = g_wuT + (size_t)e*DD*HH;
    Out = g_hid;
  } else { Wg = g_sgT; Wu = g_suT; Out = g_shid; }

  if (tid < BM){
    int t = ROUTED ? g_row_token[row0+tid] : (row0+tid);
    rtok[tid] = t < 0 ? 0 : t;
  }
  __syncthreads();

  const int NCH = HH/32;   // 32
  auto ld = [&](int c, int s){
    float* S = sm + s*GU_STAGEF;
    uint32_t sA = s2u(S);
    uint32_t sG = s2u(S + AS_F);
    uint32_t sU = s2u(S + AS_F + BS_F);
    int k0 = c*32;
    #pragma unroll
    for (int j=0;j<4;j++){
      int q = tid + 256*j, r = q>>3, sg = q&7;
      cpa16(sA + r*(RSTR*4) + sg*16, g_xc + (size_t)rtok[r]*HH + k0 + sg*4);
    }
    #pragma unroll
    for (int j=0;j<2;j++){
      int q = tid + 256*j, r = q>>3, sg = q&7;
      cpa16(sG + r*(RSTR*4) + sg*16, Wg + (size_t)(n0+r)*HH + k0 + sg*4);
      cpa16(sU + r*(RSTR*4) + sg*16, Wu + (size_t)(n0+r)*HH + k0 + sg*4);
    }
    cpcommit();
  };
  #pragma unroll
  for (int s=0;s<GU_S;s++) ld(s, s);

  float accg[2][4][4], accu[2][4][4];
  #pragma unroll
  for (int a=0;a<2;a++)
    #pragma unroll
    for (int b=0;b<4;b++)
      #pragma unroll
      for (int d=0;d<4;d++){ accg[a][b][d]=0.f; accu[a][b][d]=0.f; }

  for (int c=0;c<NCH;c++){
    cpwait((NCH-1-c) < (GU_S-1) ? (NCH-1-c) : (GU_S-1));
    __syncthreads();
    const float* S  = sm + (c%GU_S)*GU_STAGEF;
    const float* As = S;
    const float* Bg = S + AS_F;
    const float* Bu = S + AS_F + BS_F;
    #pragma unroll
    for (int ks=0;ks<4;ks++){
      int kp = ks*8 + 2*gc;           // physical float2 position for (gc, gc+4)
      uint32_t a[2][4];
      #pragma unroll
      for (int mt=0;mt<2;mt++){
        int r0 = wr*32 + mt*16;
        float2 lo = *(const float2*)(As + (r0+gr  )*RSTR + kp);
        float2 hi = *(const float2*)(As + (r0+gr+8)*RSTR + kp);
        a[mt][0] = __float_as_uint(lo.x);
        a[mt][1] = __float_as_uint(hi.x);
        a[mt][2] = __float_as_uint(lo.y);
        a[mt][3] = __float_as_uint(hi.y);
      }
      #pragma unroll
      for (int nt=0;nt<4;nt++){
        int n = wc*32 + nt*8 + gr;
        float2 vg = *(const float2*)(Bg + n*RSTR + kp);
        float2 vu = *(const float2*)(Bu + n*RSTR + kp);
        uint32_t bg[2] = { __float_as_uint(vg.x), __float_as_uint(vg.y) };
        uint32_t bu[2] = { __float_as_uint(vu.x), __float_as_uint(vu.y) };
        mma8(accg[0][nt], a[0], bg);
        mma8(accg[1][nt], a[1], bg);
        mma8(accu[0][nt], a[0], bu);
        mma8(accu[1][nt], a[1], bu);
      }
    }
    __syncthreads();
    if (c+GU_S < NCH) ld(c+GU_S, c%GU_S);
  }

  // epilogue: silu(g)*u, tf32-round, store with D-permutation (feeds dn GEMM K)
  const int p0 = kperm(2*gc), p1 = kperm(2*gc+1);
  #pragma unroll
  for (int mt=0;mt<2;mt++)
    #pragma unroll
    for (int nt=0;nt<4;nt++){
      int r   = row0 + wr*32 + mt*16 + gr;
      int cb  = n0 + wc*32 + nt*8;
      float g0 = accg[mt][nt][0], u0 = accu[mt][nt][0];
      float g1 = accg[mt][nt][1], u1 = accu[mt][nt][1];
      float g2 = accg[mt][nt][2], u2 = accu[mt][nt][2];
      float g3 = accg[mt][nt][3], u3 = accu[mt][nt][3];
      float* o0 = Out + (size_t)r*DD + cb;
      o0[p0] = totf(g0/(1.f+expf(-g0))*u0);
      o0[p1] = totf(g1/(1.f+expf(-g1))*u1);
      float* o1 = Out + (size_t)(r+8)*DD + cb;
      o1[p0] = totf(g2/(1.f+expf(-g2))*u2);
      o1[p1] = totf(g3/(1.f+expf(-g3))*u3);
    }
}

// ---------------- down GEMM: 128x128 tile ----------------
template<int MODE>
__global__ void __launch_bounds__(256,2) dn_mma(float* __restrict__ OutTok){
  extern __shared__ float sm[];
  __shared__ int s_tk[BM];
  const int tid = threadIdx.x, lane = tid&31, wid = tid>>5;
  const int wr = wid>>1, wc = wid&1;
  const int gr = lane>>2, gc = lane&3;
  const int row0 = blockIdx.y*BM, n0 = blockIdx.x*128;
  if (MODE==0 && row0 >= g_offsets[NE]) return;

  const float *A, *Wd;
  if (MODE == 0){
    int e = 0;
    #pragma unroll
    for (int i=1;i<NE;i++) if (row0 >= g_offsets[i]) e = i;
    Wd = g_wdT + (size_t)e*HH*DD;
    A = g_hid;
  } else { Wd = g_sdT; A = g_shid; }

  if (tid < BM)
    s_tk[tid] = (MODE==0) ? ((g_row_token[row0+tid] < 0) ? -1 : g_row_tk[row0+tid]) : 0;
  __syncthreads();

  const int NCH = DD/32;   // 86
  auto ld = [&](int c, int s){
    float* S = sm + s*DN_STAGEF;
    uint32_t sA = s2u(S);
    uint32_t sB = s2u(S + AS_F);
    int k0 = c*32;
    #pragma unroll
    for (int j=0;j<4;j++){
      int q = tid + 256*j, r = q>>3, sg = q&7;
      cpa16(sA + r*(RSTR*4) + sg*16, A  + (size_t)(row0+r)*DD + k0 + sg*4);
      cpa16(sB + r*(RSTR*4) + sg*16, Wd + (size_t)(n0 +r)*DD + k0 + sg*4);
    }
    cpcommit();
  };
  #pragma unroll
  for (int s=0;s<DN_S;s++) ld(s, s);

  float acc[2][8][4];
  #pragma unroll
  for (int a=0;a<2;a++)
    #pragma unroll
    for (int b=0;b<8;b++)
      #pragma unroll
      for (int d=0;d<4;d++) acc[a][b][d]=0.f;

  for (int c=0;c<NCH;c++){
    cpwait((NCH-1-c) < (DN_S-1) ? (NCH-1-c) : (DN_S-1));
    __syncthreads();
    const float* S  = sm + (c%DN_S)*DN_STAGEF;
    const float* As = S;
    const float* Bs = S + AS_F;
    #pragma unroll
    for (int ks=0;ks<4;ks++){
      int kp = ks*8 + 2*gc;
      uint32_t a[2][4];
      #pragma unroll
      for (int mt=0;mt<2;mt++){
        int r0 = wr*32 + mt*16;
        float2 lo = *(const float2*)(As + (r0+gr  )*RSTR + kp);
        float2 hi = *(const float2*)(As + (r0+gr+8)*RSTR + kp);
        a[mt][0] = __float_as_uint(lo.x);
        a[mt][1] = __float_as_uint(hi.x);
        a[mt][2] = __float_as_uint(lo.y);
        a[mt][3] = __float_as_uint(hi.y);
      }
      #pragma unroll
      for (int nt=0;nt<8;nt++){
        int n = wc*64 + nt*8 + gr;
        float2 vb = *(const float2*)(Bs + n*RSTR + kp);
        uint32_t b[2] = { __float_as_uint(vb.x), __float_as_uint(vb.y) };
        mma8(acc[0][nt], a[0], b);
        mma8(acc[1][nt], a[1], b);
      }
    }
    __syncthreads();
    if (c+DN_S < NCH) ld(c+DN_S, c%DN_S);
  }

  #pragma unroll
  for (int mt=0;mt<2;mt++)
    #pragma unroll
    for (int nt=0;nt<8;nt++){
      int rl  = wr*32 + mt*16 + gr;
      int col = n0 + wc*64 + nt*8 + 2*gc;
      if (MODE == 0){
        int tk0 = s_tk[rl], tk1 = s_tk[rl+8];
        if (tk0 >= 0)
          *(float2*)(g_eo + (size_t)tk0*HH + col) = make_float2(acc[mt][nt][0], acc[mt][nt][1]);
        if (tk1 >= 0)
          *(float2*)(g_eo + (size_t)tk1*HH + col) = make_float2(acc[mt][nt][2], acc[mt][nt][3]);
      } else {
        int t0 = row0 + rl, t1 = t0 + 8;
        float w00 = g_tok_w[t0*2], w01 = g_tok_w[t0*2+1];
        float w10 = g_tok_w[t1*2], w11 = g_tok_w[t1*2+1];
        float2 a0 = *(const float2*)(g_eo + (size_t)(t0*2  )*HH + col);
        float2 b0 = *(const float2*)(g_eo + (size_t)(t0*2+1)*HH + col);
        float2 a1 = *(const float2*)(g_eo + (size_t)(t1*2  )*HH + col);
        float2 b1 = *(const float2*)(g_eo + (size_t)(t1*2+1)*HH + col);
        float2 o0 = make_float2(acc[mt][nt][0] + w00*a0.x + w01*b0.x,
                                acc[mt][nt][1] + w00*a0.y + w01*b0.y);
        float2 o1 = make_float2(acc[mt][nt][2] + w10*a1.x + w11*b1.x,
                                acc[mt][nt][3] + w10*a1.y + w11*b1.y);
        *(float2*)(OutTok + (size_t)t0*HH + col) = o0;
        *(float2*)(OutTok + (size_t)t1*HH + col) = o1;
      }
    }
}

// ---------------- launch ----------------
extern "C" void kernel_launch(void* const* d_in, const int* in_sizes, int n_in,
                              void* d_out, int out_size) {
  const float* x       = (const float*)d_in[0];
  const float* gate_w  = (const float*)d_in[1];
  const float* we_gate = (const float*)d_in[2];
  const float* we_up   = (const float*)d_in[3];
  const float* we_down = (const float*)d_in[4];
  const float* sw_gate = (const float*)d_in[5];
  const float* sw_up   = (const float*)d_in[6];
  const float* sw_down = (const float*)d_in[7];
  float* out = (float*)d_out;

  cudaFuncSetAttribute(gu_mma<true >, cudaFuncAttributeMaxDynamicSharedMemorySize, GU_SMEMB);
  cudaFuncSetAttribute(gu_mma<false>, cudaFuncAttributeMaxDynamicSharedMemorySize, GU_SMEMB);
  cudaFuncSetAttribute(dn_mma<0>,     cudaFuncAttributeMaxDynamicSharedMemorySize, DN_SMEMB);
  cudaFuncSetAttribute(dn_mma<1>,     cudaFuncAttributeMaxDynamicSharedMemorySize, DN_SMEMB);

  init_kernel<<<(ROWCAP+255)/256, 256>>>();
  route_kernel<<<TT/8, 256>>>(x, gate_w);
  scan_kernel<<<1, 32>>>();
  assign_kernel<<<(TT*2+255)/256, 256>>>();
  convx_k<<<(TT*HH/8+255)/256, 256>>>(x);

  dim3 tb(32, 8);
  transpose_k<<<dim3(DD/32, HH/32, NE), tb>>>(we_gate, 0, HH, DD);
  transpose_k<<<dim3(DD/32, HH/32, NE), tb>>>(we_up,   1, HH, DD);
  transpose_k<<<dim3(HH/32, DD/32, NE), tb>>>(we_down, 2, DD, HH);
  transpose_k<<<dim3(DD/32, HH/32, 1),  tb>>>(sw_gate, 3, HH, DD);
  transpose_k<<<dim3(DD/32, HH/32, 1),  tb>>>(sw_up,   4, HH, DD);
  transpose_k<<<dim3(HH/32, DD/32, 1),  tb>>>(sw_down, 5, DD, HH);

  gu_mma<true ><<<dim3(DD/64, ROWCAP/BM), 256, GU_SMEMB>>>();
  gu_mma<false><<<dim3(DD/64, TT/BM),     256, GU_SMEMB>>>();
  dn_mma<0><<<dim3(HH/128, ROWCAP/BM), 256, DN_SMEMB>>>(nullptr);
  dn_mma<1><<<dim3(HH/128, TT/BM),     256, DN_SMEMB>>>(out);
}